// round 7
// baseline (speedup 1.0000x reference)
#include <cuda_runtime.h>
#include <cuda_fp16.h>
#include <cstdint>

// ---------------------------------------------------------------------------
// MTRNN cell as ONE block-sparse fp16 GEMM (mma.sync.m16n8k16, legacy path).
// R7: convoy-breaking schedule. R6 ncu showed tensor 37.9% with the kernel
// exactly co-bound tensor(1024cyc)/smem-crossbar(1000cyc) per CTA-ktile but
// only 44% of the overlapped floor: barrier-aligned LDS bursts serialized
// the two pipes. Changes: (1) per-nt JIT B-frag loads (2-deep reg pipeline,
// -24 live regs); (2) warp-staggered kt2 order (wm parity); (3) cp.async
// issue moved between the kt2 halves. Sparsity k-skip + 32-bit offset
// walking retained from R6.
// ---------------------------------------------------------------------------

#define BATCH 16384
#define KDIM  1344
#define NPAD  1408
#define NREAL 1344
#define NS    3

#define NT8   (NPAD / 8)         // 176
#define KT32  (KDIM / 32)        // 42

#define OFF_OUT  0
#define OFF_IO   (BATCH * 64)
#define OFF_FAST (OFF_IO + BATCH * 512)
#define OFF_SLOW (OFF_FAST + BATCH * 512)

#define A_STRIDE_B  160
#define A_BYTES     (128 * A_STRIDE_B)      // 20480
#define B_BYTES     16384
#define STAGE_BYTES (A_BYTES + B_BYTES)     // 36864
#define SM_TOTAL    (NS * STAGE_BYTES)      // 110592

#define ABLKS 21504
#define WBLKS 3696
#define BBLKS 6

__device__ __half g_Ah[(size_t)BATCH * KDIM];
__device__ uint32_t g_WfragH[(size_t)NT8 * KT32 * 32 * 4];
__device__ __align__(16) float g_bias[NPAD];

__device__ __forceinline__ uint32_t smem_u32(const void* p) {
    uint32_t a;
    asm("{ .reg .u64 t; cvta.to.shared.u64 t, %1; cvt.u32.u64 %0, t; }"
        : "=r"(a) : "l"(p));
    return a;
}
__device__ __forceinline__ void cpa16(uint32_t dst, const void* src) {
    asm volatile("cp.async.cg.shared.global [%0], [%1], 16;" :: "r"(dst), "l"(src));
}
#define CP_COMMIT() asm volatile("cp.async.commit_group;" ::: "memory")
#define CP_WAIT1()  asm volatile("cp.async.wait_group 1;" ::: "memory")

__device__ __forceinline__ void mma_f16(float* c, uint32_t a0, uint32_t a1,
                                        uint32_t a2, uint32_t a3,
                                        uint32_t b0, uint32_t b1) {
    asm volatile(
        "mma.sync.aligned.m16n8k16.row.col.f32.f16.f16.f32 "
        "{%0,%1,%2,%3}, {%4,%5,%6,%7}, {%8,%9}, {%0,%1,%2,%3};\n"
        : "+f"(c[0]), "+f"(c[1]), "+f"(c[2]), "+f"(c[3])
        : "r"(a0), "r"(a1), "r"(a2), "r"(a3), "r"(b0), "r"(b1));
}

// ---------------------------------------------------------------------------
__device__ __forceinline__ float w_lookup(
    int k, int n,
    const float* W_in_io,   const float* W_io_io,   const float* W_fast_io,
    const float* W_io_fast, const float* W_fast_fast, const float* W_slow_fast,
    const float* W_fast_slow, const float* W_slow_slow, const float* W_io_out)
{
    float v = 0.0f;
    if (n < 64) {
        if (k >= 64 && k < 576)        v = W_io_out[(k - 64) * 64 + n];
    } else if (n < 576) {
        int nn = n - 64;
        if (k < 64)                    v = W_in_io[k * 512 + nn];
        else if (k < 576)              v = W_io_io[(k - 64) * 512 + nn];
        else if (k < 1088)             v = W_fast_io[(k - 576) * 512 + nn];
    } else if (n < 1088) {
        int nn = n - 576;
        if (k >= 64 && k < 576)        v = W_io_fast[(k - 64) * 512 + nn];
        else if (k >= 576 && k < 1088) v = W_fast_fast[(k - 576) * 512 + nn];
        else if (k >= 1088)            v = W_slow_fast[(k - 1088) * 512 + nn];
    } else if (n < NREAL) {
        int nn = n - 1088;
        if (k >= 576 && k < 1088)      v = W_fast_slow[(k - 576) * 256 + nn];
        else if (k >= 1088)            v = W_slow_slow[(k - 1088) * 256 + nn];
    }
    return v;
}

__global__ void prep(
    const float* __restrict__ inp,    const float* __restrict__ io_h,
    const float* __restrict__ fast_h, const float* __restrict__ slow_h,
    const float* __restrict__ W_in_io,   const float* __restrict__ W_io_io,
    const float* __restrict__ W_fast_io, const float* __restrict__ W_io_fast,
    const float* __restrict__ W_fast_fast, const float* __restrict__ W_slow_fast,
    const float* __restrict__ W_fast_slow, const float* __restrict__ W_slow_slow,
    const float* __restrict__ W_io_out,
    const float* __restrict__ b_in_io,   const float* __restrict__ b_io_io,
    const float* __restrict__ b_fast_io, const float* __restrict__ b_io_fast,
    const float* __restrict__ b_fast_fast, const float* __restrict__ b_slow_fast,
    const float* __restrict__ b_fast_slow, const float* __restrict__ b_slow_slow,
    const float* __restrict__ b_io_out)
{
    int bid = blockIdx.x;
    if (bid < ABLKS) {
        int idx = bid * 256 + threadIdx.x;
        int row = idx / 336;
        int o   = (idx % 336) * 4;
        int blk = o >> 4;
        int tg  = (o & 15) >> 2;
        int k0  = blk * 16 + 2 * tg;
        const float* src; int ld, kb;
        if (k0 < 64)        { src = inp;    ld = 64;  kb = k0; }
        else if (k0 < 576)  { src = io_h;   ld = 512; kb = k0 - 64; }
        else if (k0 < 1088) { src = fast_h; ld = 512; kb = k0 - 576; }
        else                { src = slow_h; ld = 256; kb = k0 - 1088; }
        float2 p0 = *(const float2*)(src + (size_t)row * ld + kb);
        float2 p1 = *(const float2*)(src + (size_t)row * ld + kb + 8);
        __half2* dst = (__half2*)(g_Ah + (size_t)row * KDIM + o);
        dst[0] = __floats2half2_rn(p0.x, p0.y);
        dst[1] = __floats2half2_rn(p1.x, p1.y);
    } else if (bid < ABLKS + WBLKS) {
        int idx  = (bid - ABLKS) * 256 + threadIdx.x;
        int u    = idx & 3;
        int lane = (idx >> 2) & 31;
        int t    = idx >> 7;
        int kt32 = t % KT32;
        int nt   = t / KT32;
        int n    = nt * 8 + (lane >> 2);
        int tg   = lane & 3;
        int kb   = kt32 * 32 + (u >> 1) * 16;
        int k    = kb + 2 * tg + (u & 1) * 8;
        float lo = w_lookup(k, n, W_in_io, W_io_io, W_fast_io, W_io_fast,
                            W_fast_fast, W_slow_fast, W_fast_slow, W_slow_slow,
                            W_io_out);
        float hi = w_lookup(k + 1, n, W_in_io, W_io_io, W_fast_io, W_io_fast,
                            W_fast_fast, W_slow_fast, W_fast_slow, W_slow_slow,
                            W_io_out);
        __half2 h = __floats2half2_rn(lo, hi);
        g_WfragH[idx] = *(uint32_t*)&h;
    } else {
        int n = (bid - ABLKS - WBLKS) * 256 + threadIdx.x;
        if (n >= NPAD) return;
        float v = 0.0f;
        if (n < 64)        v = b_io_out[n];
        else if (n < 576)  { int nn = n - 64;   v = b_in_io[nn] + b_io_io[nn] + b_fast_io[nn]; }
        else if (n < 1088) { int nn = n - 576;  v = b_io_fast[nn] + b_fast_fast[nn] + b_slow_fast[nn]; }
        else if (n < NREAL){ int nn = n - 1088; v = b_slow_slow[nn] + b_fast_slow[nn]; }
        g_bias[n] = v;
    }
}

// ---------------------------------------------------------------------------
__global__ __launch_bounds__(256, 2) void mtrnn_mma(
    const float* __restrict__ io_h, const float* __restrict__ fast_h,
    const float* __restrict__ slow_h, float* __restrict__ out)
{
    extern __shared__ char smem[];
    const uint32_t sb = smem_u32(smem);

    const int tid  = threadIdx.x;
    const int lane = tid & 31;
    const int warp = tid >> 5;
    const int wm   = warp & 3;
    const int wn   = warp >> 2;
    const int g    = lane >> 2;
    const int tg   = lane & 3;

    const int n0 = blockIdx.x * 128;
    const int m0 = blockIdx.y * 128;
    const int nt8_0 = blockIdx.x * 16;

    // ---- exact k-range for this n-block (packed W block sparsity) ----
    int nhi = n0 + 128; if (nhi > NREAL) nhi = NREAL;
    int klo = KDIM, khi = 0;
    if (n0 < 64)                 { if (64 < klo) klo = 64;  if (576 > khi) khi = 576; }
    if (n0 < 576 && nhi > 64)    { klo = 0;                 if (1088 > khi) khi = 1088; }
    if (n0 < 1088 && nhi > 576)  { if (64 < klo) klo = 64;  khi = KDIM; }
    if (nhi > 1088)              { if (576 < klo) klo = 576; khi = KDIM; }
    const int kt_lo = klo >> 6;
    const int nkt   = ((khi + 63) >> 6) - kt_lo;    // 12..21

    float acc[2][8][4];
#pragma unroll
    for (int mt = 0; mt < 2; mt++)
#pragma unroll
        for (int nt = 0; nt < 8; nt++)
#pragma unroll
            for (int i = 0; i < 4; i++) acc[mt][nt][i] = 0.0f;

    // ---- per-thread load descriptors: 32-bit byte offsets, const strides --
    const char* aBase = (const char*)g_Ah;
    const char* bBase = (const char*)g_WfragH;
    uint32_t aSm[4], aGo[4], bSm[4], bGo[4];
#pragma unroll
    for (int i = 0; i < 4; i++) {
        int idx = tid + i * 256;
        int row = idx >> 3, seg = idx & 7;
        aSm[i] = (uint32_t)(row * A_STRIDE_B + seg * 16);
        aGo[i] = ((uint32_t)(m0 + row) * KDIM + (uint32_t)kt_lo * 64 + seg * 8) * 2;
        int nt = idx >> 6, rem = idx & 63;
        bSm[i] = (uint32_t)(A_BYTES + idx * 16);
        bGo[i] = (((uint32_t)(nt8_0 + nt) * KT32 + (uint32_t)kt_lo * 2 + (rem >> 5)) * 32
                  + (rem & 31)) * 16;
    }

    auto load_slot = [&](int slot) {
        uint32_t aD = sb + slot * STAGE_BYTES;
#pragma unroll
        for (int i = 0; i < 4; i++) cpa16(aD + aSm[i], aBase + aGo[i]);
#pragma unroll
        for (int i = 0; i < 4; i++) cpa16(aD + bSm[i], bBase + bGo[i]);
#pragma unroll
        for (int i = 0; i < 4; i++) { aGo[i] += 128; bGo[i] += 1024; }
    };

    // one kt2-half of a k-tile: JIT per-nt B loads, 2-deep; A preloaded
    auto compute_half = [&](int slot, int h) {
        const uint2*  As2 = (const uint2*)(smem + slot * STAGE_BYTES);
        const float4* Bs4 = (const float4*)(smem + slot * STAGE_BYTES + A_BYTES);
        const int kt2 = h ^ (wm & 1);                // warp-staggered k order
        uint2 alo[2][2], ahi[2][2];                  // [kk][mt]
#pragma unroll
        for (int kk = 0; kk < 2; kk++)
#pragma unroll
            for (int mt = 0; mt < 2; mt++) {
                int r = wm * 32 + mt * 16 + g;
                int o = r * 20 + kt2 * 8 + kk * 4 + tg;
                alo[kk][mt] = As2[o];
                ahi[kk][mt] = As2[o + 8 * 20];
            }
        float4 bcur = Bs4[((wn * 8 + 0) * 2 + kt2) * 32 + lane];
#pragma unroll
        for (int nt = 0; nt < 8; nt++) {
            float4 bnxt;
            if (nt < 7) bnxt = Bs4[((wn * 8 + nt + 1) * 2 + kt2) * 32 + lane];
#pragma unroll
            for (int kk = 0; kk < 2; kk++) {
                uint32_t b0 = kk ? __float_as_uint(bcur.z) : __float_as_uint(bcur.x);
                uint32_t b1 = kk ? __float_as_uint(bcur.w) : __float_as_uint(bcur.y);
#pragma unroll
                for (int mt = 0; mt < 2; mt++)
                    mma_f16(acc[mt][nt], alo[kk][mt].x, ahi[kk][mt].x,
                            alo[kk][mt].y, ahi[kk][mt].y, b0, b1);
            }
            bcur = bnxt;
        }
    };

    // ---- pipelined mainloop, unrolled by 3 so stage slots are literal ----
    load_slot(0); CP_COMMIT();
    load_slot(1); CP_COMMIT();
    int ld = 2;

#define STEP(J) do {                                   \
        CP_WAIT1(); __syncthreads();                   \
        compute_half(J, 0);                            \
        if (ld < nkt) load_slot(((J) + 2) % 3);        \
        CP_COMMIT();                                   \
        compute_half(J, 1);                            \
        ld++;                                          \
    } while (0)

    int it = 0;
    while (it + 3 <= nkt) { STEP(0); STEP(1); STEP(2); it += 3; }
    if (it < nkt) { STEP(0); it++; }
    if (it < nkt) { STEP(1); it++; }
#undef STEP

    // ---- epilogue: bias + leak + tanh, float2 stores ----
#pragma unroll
    for (int nt = 0; nt < 8; nt++) {
        int gb = n0 + wn * 64 + nt * 8;
        if (gb >= NREAL) continue;
        int gn = gb + tg * 2;
        float2 bi = *(const float2*)&g_bias[gn];
#pragma unroll
        for (int mt = 0; mt < 2; mt++) {
            int br = m0 + wm * 32 + mt * 16 + g;
#pragma unroll
            for (int hh = 0; hh < 2; hh++) {
                int b = br + hh * 8;
                float s0 = acc[mt][nt][hh * 2 + 0] + bi.x;
                float s1 = acc[mt][nt][hh * 2 + 1] + bi.y;
                float2 o;
                if (gb < 64) {
                    o.x = tanhf(s0); o.y = tanhf(s1);
                    *(float2*)&out[OFF_OUT + (size_t)b * 64 + gn] = o;
                } else if (gb < 576) {
                    int nn = gn - 64;
                    float2 h = *(const float2*)&io_h[(size_t)b * 512 + nn];
                    o.x = tanhf(0.5f * h.x + 0.5f * s0);
                    o.y = tanhf(0.5f * h.y + 0.5f * s1);
                    *(float2*)&out[OFF_IO + (size_t)b * 512 + nn] = o;
                } else if (gb < 1088) {
                    int nn = gn - 576;
                    float2 h = *(const float2*)&fast_h[(size_t)b * 512 + nn];
                    o.x = tanhf(0.8f * h.x + 0.2f * s0);
                    o.y = tanhf(0.8f * h.y + 0.2f * s1);
                    *(float2*)&out[OFF_FAST + (size_t)b * 512 + nn] = o;
                } else {
                    int nn = gn - 1088;
                    const float cs = 1.0f - 1.0f / 70.0f, is = 1.0f / 70.0f;
                    float2 h = *(const float2*)&slow_h[(size_t)b * 256 + nn];
                    o.x = tanhf(cs * h.x + is * s0);
                    o.y = tanhf(cs * h.y + is * s1);
                    *(float2*)&out[OFF_SLOW + (size_t)b * 256 + nn] = o;
                }
            }
        }
    }
}

// ---------------------------------------------------------------------------
extern "C" void kernel_launch(void* const* d_in, const int* in_sizes, int n_in,
                              void* d_out, int out_size)
{
    const float* input       = (const float*)d_in[0];
    const float* io_h        = (const float*)d_in[1];
    const float* fast_h      = (const float*)d_in[2];
    const float* slow_h      = (const float*)d_in[3];
    const float* W_in_io     = (const float*)d_in[4];
    const float* b_in_io     = (const float*)d_in[5];
    const float* W_io_fast   = (const float*)d_in[6];
    const float* b_io_fast   = (const float*)d_in[7];
    const float* W_fast_fast = (const float*)d_in[8];
    const float* b_fast_fast = (const float*)d_in[9];
    const float* W_fast_slow = (const float*)d_in[10];
    const float* b_fast_slow = (const float*)d_in[11];
    const float* W_slow_slow = (const float*)d_in[12];
    const float* b_slow_slow = (const float*)d_in[13];
    const float* W_slow_fast = (const float*)d_in[14];
    const float* b_slow_fast = (const float*)d_in[15];
    const float* W_fast_io   = (const float*)d_in[16];
    const float* b_fast_io   = (const float*)d_in[17];
    const float* W_io_io     = (const float*)d_in[18];
    const float* b_io_io     = (const float*)d_in[19];
    const float* W_io_out    = (const float*)d_in[20];
    const float* b_io_out    = (const float*)d_in[21];

    cudaFuncSetAttribute(mtrnn_mma, cudaFuncAttributeMaxDynamicSharedMemorySize,
                         SM_TOTAL);

    prep<<<ABLKS + WBLKS + BBLKS, 256>>>(
        input, io_h, fast_h, slow_h,
        W_in_io, W_io_io, W_fast_io, W_io_fast, W_fast_fast,
        W_slow_fast, W_fast_slow, W_slow_slow, W_io_out,
        b_in_io, b_io_io, b_fast_io, b_io_fast, b_fast_fast,
        b_slow_fast, b_fast_slow, b_slow_slow, b_io_out);

    dim3 grid(NPAD / 128, BATCH / 128);
    mtrnn_mma<<<grid, 256, SM_TOTAL>>>(io_h, fast_h, slow_h, (float*)d_out);
}

// round 8
// speedup vs baseline: 1.1769x; 1.1769x over previous
#include <cuda_runtime.h>
#include <cuda_fp16.h>
#include <cstdint>

// ---------------------------------------------------------------------------
// MTRNN cell as ONE block-sparse fp16 GEMM (mma.sync.m16n8k16, legacy path).
// R8: rebalanced warp tiling 2M x 4N (warp tile 64x32). Crossbar per warp per
// k-tile drops 80->64 cyc (A:16 LDS.64 + B:8 LDS.128), making tensor (1024
// cyc/SM/k-tile) the dominant pipe with slack for overlap. kt2 order is
// wm-parity staggered (hoisted XOR, NO register rotation -- R7's MOV chains
// were the regression). cp.async issued between kt2 halves. Sparsity k-skip
// + 32-bit offset walking retained from R6.
// ---------------------------------------------------------------------------

#define BATCH 16384
#define KDIM  1344
#define NPAD  1408
#define NREAL 1344
#define NS    3

#define NT8   (NPAD / 8)         // 176
#define KT32  (KDIM / 32)        // 42

#define OFF_OUT  0
#define OFF_IO   (BATCH * 64)
#define OFF_FAST (OFF_IO + BATCH * 512)
#define OFF_SLOW (OFF_FAST + BATCH * 512)

#define A_STRIDE_B  160
#define A_BYTES     (128 * A_STRIDE_B)      // 20480
#define B_BYTES     16384
#define STAGE_BYTES (A_BYTES + B_BYTES)     // 36864
#define SM_TOTAL    (NS * STAGE_BYTES)      // 110592

#define ABLKS 21504
#define WBLKS 3696
#define BBLKS 6

__device__ __half g_Ah[(size_t)BATCH * KDIM];
__device__ uint32_t g_WfragH[(size_t)NT8 * KT32 * 32 * 4];
__device__ __align__(16) float g_bias[NPAD];

__device__ __forceinline__ uint32_t smem_u32(const void* p) {
    uint32_t a;
    asm("{ .reg .u64 t; cvta.to.shared.u64 t, %1; cvt.u32.u64 %0, t; }"
        : "=r"(a) : "l"(p));
    return a;
}
__device__ __forceinline__ void cpa16(uint32_t dst, const void* src) {
    asm volatile("cp.async.cg.shared.global [%0], [%1], 16;" :: "r"(dst), "l"(src));
}
#define CP_COMMIT() asm volatile("cp.async.commit_group;" ::: "memory")
#define CP_WAIT1()  asm volatile("cp.async.wait_group 1;" ::: "memory")

__device__ __forceinline__ void mma_f16(float* c, uint32_t a0, uint32_t a1,
                                        uint32_t a2, uint32_t a3,
                                        uint32_t b0, uint32_t b1) {
    asm volatile(
        "mma.sync.aligned.m16n8k16.row.col.f32.f16.f16.f32 "
        "{%0,%1,%2,%3}, {%4,%5,%6,%7}, {%8,%9}, {%0,%1,%2,%3};\n"
        : "+f"(c[0]), "+f"(c[1]), "+f"(c[2]), "+f"(c[3])
        : "r"(a0), "r"(a1), "r"(a2), "r"(a3), "r"(b0), "r"(b1));
}

// ---------------------------------------------------------------------------
__device__ __forceinline__ float w_lookup(
    int k, int n,
    const float* W_in_io,   const float* W_io_io,   const float* W_fast_io,
    const float* W_io_fast, const float* W_fast_fast, const float* W_slow_fast,
    const float* W_fast_slow, const float* W_slow_slow, const float* W_io_out)
{
    float v = 0.0f;
    if (n < 64) {
        if (k >= 64 && k < 576)        v = W_io_out[(k - 64) * 64 + n];
    } else if (n < 576) {
        int nn = n - 64;
        if (k < 64)                    v = W_in_io[k * 512 + nn];
        else if (k < 576)              v = W_io_io[(k - 64) * 512 + nn];
        else if (k < 1088)             v = W_fast_io[(k - 576) * 512 + nn];
    } else if (n < 1088) {
        int nn = n - 576;
        if (k >= 64 && k < 576)        v = W_io_fast[(k - 64) * 512 + nn];
        else if (k >= 576 && k < 1088) v = W_fast_fast[(k - 576) * 512 + nn];
        else if (k >= 1088)            v = W_slow_fast[(k - 1088) * 512 + nn];
    } else if (n < NREAL) {
        int nn = n - 1088;
        if (k >= 576 && k < 1088)      v = W_fast_slow[(k - 576) * 256 + nn];
        else if (k >= 1088)            v = W_slow_slow[(k - 1088) * 256 + nn];
    }
    return v;
}

__global__ void prep(
    const float* __restrict__ inp,    const float* __restrict__ io_h,
    const float* __restrict__ fast_h, const float* __restrict__ slow_h,
    const float* __restrict__ W_in_io,   const float* __restrict__ W_io_io,
    const float* __restrict__ W_fast_io, const float* __restrict__ W_io_fast,
    const float* __restrict__ W_fast_fast, const float* __restrict__ W_slow_fast,
    const float* __restrict__ W_fast_slow, const float* __restrict__ W_slow_slow,
    const float* __restrict__ W_io_out,
    const float* __restrict__ b_in_io,   const float* __restrict__ b_io_io,
    const float* __restrict__ b_fast_io, const float* __restrict__ b_io_fast,
    const float* __restrict__ b_fast_fast, const float* __restrict__ b_slow_fast,
    const float* __restrict__ b_fast_slow, const float* __restrict__ b_slow_slow,
    const float* __restrict__ b_io_out)
{
    int bid = blockIdx.x;
    if (bid < ABLKS) {
        int idx = bid * 256 + threadIdx.x;
        int row = idx / 336;
        int o   = (idx % 336) * 4;
        int blk = o >> 4;
        int tg  = (o & 15) >> 2;
        int k0  = blk * 16 + 2 * tg;
        const float* src; int ld, kb;
        if (k0 < 64)        { src = inp;    ld = 64;  kb = k0; }
        else if (k0 < 576)  { src = io_h;   ld = 512; kb = k0 - 64; }
        else if (k0 < 1088) { src = fast_h; ld = 512; kb = k0 - 576; }
        else                { src = slow_h; ld = 256; kb = k0 - 1088; }
        float2 p0 = *(const float2*)(src + (size_t)row * ld + kb);
        float2 p1 = *(const float2*)(src + (size_t)row * ld + kb + 8);
        __half2* dst = (__half2*)(g_Ah + (size_t)row * KDIM + o);
        dst[0] = __floats2half2_rn(p0.x, p0.y);
        dst[1] = __floats2half2_rn(p1.x, p1.y);
    } else if (bid < ABLKS + WBLKS) {
        int idx  = (bid - ABLKS) * 256 + threadIdx.x;
        int u    = idx & 3;
        int lane = (idx >> 2) & 31;
        int t    = idx >> 7;
        int kt32 = t % KT32;
        int nt   = t / KT32;
        int n    = nt * 8 + (lane >> 2);
        int tg   = lane & 3;
        int kb   = kt32 * 32 + (u >> 1) * 16;
        int k    = kb + 2 * tg + (u & 1) * 8;
        float lo = w_lookup(k, n, W_in_io, W_io_io, W_fast_io, W_io_fast,
                            W_fast_fast, W_slow_fast, W_fast_slow, W_slow_slow,
                            W_io_out);
        float hi = w_lookup(k + 1, n, W_in_io, W_io_io, W_fast_io, W_io_fast,
                            W_fast_fast, W_slow_fast, W_fast_slow, W_slow_slow,
                            W_io_out);
        __half2 h = __floats2half2_rn(lo, hi);
        g_WfragH[idx] = *(uint32_t*)&h;
    } else {
        int n = (bid - ABLKS - WBLKS) * 256 + threadIdx.x;
        if (n >= NPAD) return;
        float v = 0.0f;
        if (n < 64)        v = b_io_out[n];
        else if (n < 576)  { int nn = n - 64;   v = b_in_io[nn] + b_io_io[nn] + b_fast_io[nn]; }
        else if (n < 1088) { int nn = n - 576;  v = b_io_fast[nn] + b_fast_fast[nn] + b_slow_fast[nn]; }
        else if (n < NREAL){ int nn = n - 1088; v = b_slow_slow[nn] + b_fast_slow[nn]; }
        g_bias[n] = v;
    }
}

// ---------------------------------------------------------------------------
__global__ __launch_bounds__(256, 2) void mtrnn_mma(
    const float* __restrict__ io_h, const float* __restrict__ fast_h,
    const float* __restrict__ slow_h, float* __restrict__ out)
{
    extern __shared__ char smem[];
    const uint32_t sb = smem_u32(smem);

    const int tid  = threadIdx.x;
    const int lane = tid & 31;
    const int warp = tid >> 5;
    const int wm   = warp & 1;      // 0..1 : 64-row slab
    const int wn   = warp >> 1;     // 0..3 : 32-col slab
    const int g    = lane >> 2;
    const int tg   = lane & 3;

    const int n0 = blockIdx.x * 128;
    const int m0 = blockIdx.y * 128;
    const int nt8_0 = blockIdx.x * 16;

    // ---- exact k-range for this n-block (packed W block sparsity) ----
    int nhi = n0 + 128; if (nhi > NREAL) nhi = NREAL;
    int klo = KDIM, khi = 0;
    if (n0 < 64)                 { if (64 < klo) klo = 64;  if (576 > khi) khi = 576; }
    if (n0 < 576 && nhi > 64)    { klo = 0;                 if (1088 > khi) khi = 1088; }
    if (n0 < 1088 && nhi > 576)  { if (64 < klo) klo = 64;  khi = KDIM; }
    if (nhi > 1088)              { if (576 < klo) klo = 576; khi = KDIM; }
    const int kt_lo = klo >> 6;
    const int nkt   = ((khi + 63) >> 6) - kt_lo;    // 12..21

    float acc[4][4][4];             // [mt][nt][frag]
#pragma unroll
    for (int mt = 0; mt < 4; mt++)
#pragma unroll
        for (int nt = 0; nt < 4; nt++)
#pragma unroll
            for (int i = 0; i < 4; i++) acc[mt][nt][i] = 0.0f;

    // ---- per-thread load descriptors: 32-bit byte offsets, const strides --
    const char* aBase = (const char*)g_Ah;
    const char* bBase = (const char*)g_WfragH;
    uint32_t aSm[4], aGo[4], bSm[4], bGo[4];
#pragma unroll
    for (int i = 0; i < 4; i++) {
        int idx = tid + i * 256;
        int row = idx >> 3, seg = idx & 7;
        aSm[i] = (uint32_t)(row * A_STRIDE_B + seg * 16);
        aGo[i] = ((uint32_t)(m0 + row) * KDIM + (uint32_t)kt_lo * 64 + seg * 8) * 2;
        int nt = idx >> 6, rem = idx & 63;
        bSm[i] = (uint32_t)(A_BYTES + idx * 16);
        bGo[i] = (((uint32_t)(nt8_0 + nt) * KT32 + (uint32_t)kt_lo * 2 + (rem >> 5)) * 32
                  + (rem & 31)) * 16;
    }

    auto load_slot = [&](int slot) {
        uint32_t aD = sb + slot * STAGE_BYTES;
#pragma unroll
        for (int i = 0; i < 4; i++) cpa16(aD + aSm[i], aBase + aGo[i]);
#pragma unroll
        for (int i = 0; i < 4; i++) cpa16(aD + bSm[i], bBase + bGo[i]);
#pragma unroll
        for (int i = 0; i < 4; i++) { aGo[i] += 128; bGo[i] += 1024; }
    };

    // one kt2-half: B frags up front (4 LDS.128), A frags per-mt (low liveness)
    auto compute_half = [&](int slot, int h) {
        const uint2*  As2 = (const uint2*)(smem + slot * STAGE_BYTES);
        const float4* Bs4 = (const float4*)(smem + slot * STAGE_BYTES + A_BYTES);
        const int kt2 = h ^ wm;                  // warp-staggered k order
        float4 bf[4];
#pragma unroll
        for (int nt = 0; nt < 4; nt++)
            bf[nt] = Bs4[((wn * 4 + nt) * 2 + kt2) * 32 + lane];
#pragma unroll
        for (int mt = 0; mt < 4; mt++) {
            int r = wm * 64 + mt * 16 + g;
            int o = r * 20 + kt2 * 8 + tg;
            uint2 alo0 = As2[o];
            uint2 ahi0 = As2[o + 8 * 20];
            uint2 alo1 = As2[o + 4];
            uint2 ahi1 = As2[o + 4 + 8 * 20];
#pragma unroll
            for (int nt = 0; nt < 4; nt++) {
                mma_f16(acc[mt][nt], alo0.x, ahi0.x, alo0.y, ahi0.y,
                        __float_as_uint(bf[nt].x), __float_as_uint(bf[nt].y));
                mma_f16(acc[mt][nt], alo1.x, ahi1.x, alo1.y, ahi1.y,
                        __float_as_uint(bf[nt].z), __float_as_uint(bf[nt].w));
            }
        }
    };

    // ---- pipelined mainloop, unrolled by 3 so stage slots are literal ----
    load_slot(0); CP_COMMIT();
    load_slot(1); CP_COMMIT();
    int ld = 2;

#define STEP(J) do {                                   \
        CP_WAIT1(); __syncthreads();                   \
        compute_half(J, 0);                            \
        if (ld < nkt) load_slot(((J) + 2) % 3);        \
        CP_COMMIT();                                   \
        compute_half(J, 1);                            \
        ld++;                                          \
    } while (0)

    int it = 0;
    while (it + 3 <= nkt) { STEP(0); STEP(1); STEP(2); it += 3; }
    if (it < nkt) { STEP(0); it++; }
    if (it < nkt) { STEP(1); it++; }
#undef STEP

    // ---- epilogue: bias + leak + tanh, float2 stores ----
#pragma unroll
    for (int nt = 0; nt < 4; nt++) {
        int gb = n0 + wn * 32 + nt * 8;
        if (gb >= NREAL) continue;
        int gn = gb + tg * 2;
        float2 bi = *(const float2*)&g_bias[gn];
#pragma unroll
        for (int mt = 0; mt < 4; mt++) {
            int br = m0 + wm * 64 + mt * 16 + g;
#pragma unroll
            for (int hh = 0; hh < 2; hh++) {
                int b = br + hh * 8;
                float s0 = acc[mt][nt][hh * 2 + 0] + bi.x;
                float s1 = acc[mt][nt][hh * 2 + 1] + bi.y;
                float2 o;
                if (gb < 64) {
                    o.x = tanhf(s0); o.y = tanhf(s1);
                    *(float2*)&out[OFF_OUT + (size_t)b * 64 + gn] = o;
                } else if (gb < 576) {
                    int nn = gn - 64;
                    float2 h = *(const float2*)&io_h[(size_t)b * 512 + nn];
                    o.x = tanhf(0.5f * h.x + 0.5f * s0);
                    o.y = tanhf(0.5f * h.y + 0.5f * s1);
                    *(float2*)&out[OFF_IO + (size_t)b * 512 + nn] = o;
                } else if (gb < 1088) {
                    int nn = gn - 576;
                    float2 h = *(const float2*)&fast_h[(size_t)b * 512 + nn];
                    o.x = tanhf(0.8f * h.x + 0.2f * s0);
                    o.y = tanhf(0.8f * h.y + 0.2f * s1);
                    *(float2*)&out[OFF_FAST + (size_t)b * 512 + nn] = o;
                } else {
                    int nn = gn - 1088;
                    const float cs = 1.0f - 1.0f / 70.0f, is = 1.0f / 70.0f;
                    float2 h = *(const float2*)&slow_h[(size_t)b * 256 + nn];
                    o.x = tanhf(cs * h.x + is * s0);
                    o.y = tanhf(cs * h.y + is * s1);
                    *(float2*)&out[OFF_SLOW + (size_t)b * 256 + nn] = o;
                }
            }
        }
    }
}

// ---------------------------------------------------------------------------
extern "C" void kernel_launch(void* const* d_in, const int* in_sizes, int n_in,
                              void* d_out, int out_size)
{
    const float* input       = (const float*)d_in[0];
    const float* io_h        = (const float*)d_in[1];
    const float* fast_h      = (const float*)d_in[2];
    const float* slow_h      = (const float*)d_in[3];
    const float* W_in_io     = (const float*)d_in[4];
    const float* b_in_io     = (const float*)d_in[5];
    const float* W_io_fast   = (const float*)d_in[6];
    const float* b_io_fast   = (const float*)d_in[7];
    const float* W_fast_fast = (const float*)d_in[8];
    const float* b_fast_fast = (const float*)d_in[9];
    const float* W_fast_slow = (const float*)d_in[10];
    const float* b_fast_slow = (const float*)d_in[11];
    const float* W_slow_slow = (const float*)d_in[12];
    const float* b_slow_slow = (const float*)d_in[13];
    const float* W_slow_fast = (const float*)d_in[14];
    const float* b_slow_fast = (const float*)d_in[15];
    const float* W_fast_io   = (const float*)d_in[16];
    const float* b_fast_io   = (const float*)d_in[17];
    const float* W_io_io     = (const float*)d_in[18];
    const float* b_io_io     = (const float*)d_in[19];
    const float* W_io_out    = (const float*)d_in[20];
    const float* b_io_out    = (const float*)d_in[21];

    cudaFuncSetAttribute(mtrnn_mma, cudaFuncAttributeMaxDynamicSharedMemorySize,
                         SM_TOTAL);

    prep<<<ABLKS + WBLKS + BBLKS, 256>>>(
        input, io_h, fast_h, slow_h,
        W_in_io, W_io_io, W_fast_io, W_io_fast, W_fast_fast,
        W_slow_fast, W_fast_slow, W_slow_slow, W_io_out,
        b_in_io, b_io_io, b_fast_io, b_io_fast, b_fast_fast,
        b_slow_fast, b_fast_slow, b_slow_slow, b_io_out);

    dim3 grid(NPAD / 128, BATCH / 128);
    mtrnn_mma<<<grid, 256, SM_TOTAL>>>(io_h, fast_h, slow_h, (float*)d_out);
}

// round 9
// speedup vs baseline: 1.2799x; 1.0875x over previous
#include <cuda_runtime.h>
#include <cuda_fp16.h>
#include <cstdint>

// ---------------------------------------------------------------------------
// MTRNN cell as ONE block-sparse fp16 GEMM (mma.sync.m16n8k16, legacy path).
// R9: A ALSO pre-permuted into m16n8k16 fragment-interleaved gmem layout
// (B already was). A-frag loads become 8 LDS.128/warp/ktile (was 32 LDS.64);
// A staging is a linear 16KB copy with one 32-bit base register walking by
// +16KB. R8 ncu showed both tensor (41.8%) and crossbar (49.1%) unsaturated
// with issue 40.6% -> latency/issue-bound at 16 warps/SM; this cuts ~24
// instrs + address ALU per warp per ktile. Accumulation order is bit-
// identical to R8 (rel_err must stay 3.0658e-4). 2Mx4N warp tiling, NS=3
// cp.async pipeline, sparsity k-skip retained.
// ---------------------------------------------------------------------------

#define BATCH 16384
#define KDIM  1344
#define NPAD  1408
#define NREAL 1344
#define NS    3

#define NT8   (NPAD / 8)         // 176
#define KT32  (KDIM / 32)        // 42
#define K16   (KDIM / 16)        // 84

#define OFF_OUT  0
#define OFF_IO   (BATCH * 64)
#define OFF_FAST (OFF_IO + BATCH * 512)
#define OFF_SLOW (OFF_FAST + BATCH * 512)

#define A_BYTES     16384
#define B_BYTES     16384
#define STAGE_BYTES (A_BYTES + B_BYTES)     // 32768
#define SM_TOTAL    (NS * STAGE_BYTES)      // 98304

#define ABLKS 10752     // 128 mblk * 84 k16 * 8 rowtile * 32 lane / 256
#define WBLKS 3696
#define BBLKS 6

// A frags: [mblk 128][k16 84][rowtile 8][lane 32][u32 x4]
//   u0 = half2 A[r][k],A[r][k+1]; u1 = rows+8; u2 = k+8; u3 = rows+8,k+8
//   with r = mblk*128+rowtile*16+(lane>>2), k = k16*16+(lane&3)*2
__device__ uint32_t g_Af[(size_t)BATCH * KDIM / 2];
// B frags: [ntile 176][kt32 42][lane 32][u32 x4] (same as R8)
__device__ uint32_t g_WfragH[(size_t)NT8 * KT32 * 32 * 4];
__device__ __align__(16) float g_bias[NPAD];

__device__ __forceinline__ uint32_t smem_u32(const void* p) {
    uint32_t a;
    asm("{ .reg .u64 t; cvta.to.shared.u64 t, %1; cvt.u32.u64 %0, t; }"
        : "=r"(a) : "l"(p));
    return a;
}
__device__ __forceinline__ void cpa16(uint32_t dst, const void* src) {
    asm volatile("cp.async.cg.shared.global [%0], [%1], 16;" :: "r"(dst), "l"(src));
}
#define CP_COMMIT() asm volatile("cp.async.commit_group;" ::: "memory")
#define CP_WAIT1()  asm volatile("cp.async.wait_group 1;" ::: "memory")

__device__ __forceinline__ void mma_f16(float* c, uint32_t a0, uint32_t a1,
                                        uint32_t a2, uint32_t a3,
                                        uint32_t b0, uint32_t b1) {
    asm volatile(
        "mma.sync.aligned.m16n8k16.row.col.f32.f16.f16.f32 "
        "{%0,%1,%2,%3}, {%4,%5,%6,%7}, {%8,%9}, {%0,%1,%2,%3};\n"
        : "+f"(c[0]), "+f"(c[1]), "+f"(c[2]), "+f"(c[3])
        : "r"(a0), "r"(a1), "r"(a2), "r"(a3), "r"(b0), "r"(b1));
}

// ---------------------------------------------------------------------------
__device__ __forceinline__ float w_lookup(
    int k, int n,
    const float* W_in_io,   const float* W_io_io,   const float* W_fast_io,
    const float* W_io_fast, const float* W_fast_fast, const float* W_slow_fast,
    const float* W_fast_slow, const float* W_slow_slow, const float* W_io_out)
{
    float v = 0.0f;
    if (n < 64) {
        if (k >= 64 && k < 576)        v = W_io_out[(k - 64) * 64 + n];
    } else if (n < 576) {
        int nn = n - 64;
        if (k < 64)                    v = W_in_io[k * 512 + nn];
        else if (k < 576)              v = W_io_io[(k - 64) * 512 + nn];
        else if (k < 1088)             v = W_fast_io[(k - 576) * 512 + nn];
    } else if (n < 1088) {
        int nn = n - 576;
        if (k >= 64 && k < 576)        v = W_io_fast[(k - 64) * 512 + nn];
        else if (k >= 576 && k < 1088) v = W_fast_fast[(k - 576) * 512 + nn];
        else if (k >= 1088)            v = W_slow_fast[(k - 1088) * 512 + nn];
    } else if (n < NREAL) {
        int nn = n - 1088;
        if (k >= 576 && k < 1088)      v = W_fast_slow[(k - 576) * 256 + nn];
        else if (k >= 1088)            v = W_slow_slow[(k - 1088) * 256 + nn];
    }
    return v;
}

__global__ void prep(
    const float* __restrict__ inp,    const float* __restrict__ io_h,
    const float* __restrict__ fast_h, const float* __restrict__ slow_h,
    const float* __restrict__ W_in_io,   const float* __restrict__ W_io_io,
    const float* __restrict__ W_fast_io, const float* __restrict__ W_io_fast,
    const float* __restrict__ W_fast_fast, const float* __restrict__ W_slow_fast,
    const float* __restrict__ W_fast_slow, const float* __restrict__ W_slow_slow,
    const float* __restrict__ W_io_out,
    const float* __restrict__ b_in_io,   const float* __restrict__ b_io_io,
    const float* __restrict__ b_fast_io, const float* __restrict__ b_io_fast,
    const float* __restrict__ b_fast_fast, const float* __restrict__ b_slow_fast,
    const float* __restrict__ b_fast_slow, const float* __restrict__ b_slow_slow,
    const float* __restrict__ b_io_out)
{
    int bid = blockIdx.x;
    if (bid < ABLKS) {
        // ---- A frag pack: one thread = one 16B frag chunk ----
        int idx     = bid * 256 + threadIdx.x;
        int lane    = idx & 31;
        int rowtile = (idx >> 5) & 7;
        int t       = idx >> 8;
        int k16     = t % K16;
        int mblk    = t / K16;
        int row = mblk * 128 + rowtile * 16 + (lane >> 2);
        int kg  = k16 * 16 + (lane & 3) * 2;
        const float* src; int ld, kb;
        if (kg < 64)        { src = inp;    ld = 64;  kb = kg; }
        else if (kg < 576)  { src = io_h;   ld = 512; kb = kg - 64; }
        else if (kg < 1088) { src = fast_h; ld = 512; kb = kg - 576; }
        else                { src = slow_h; ld = 256; kb = kg - 1088; }
        float2 p00 = *(const float2*)(src + (size_t)row * ld + kb);
        float2 p10 = *(const float2*)(src + (size_t)(row + 8) * ld + kb);
        float2 p01 = *(const float2*)(src + (size_t)row * ld + kb + 8);
        float2 p11 = *(const float2*)(src + (size_t)(row + 8) * ld + kb + 8);
        __half2 h0 = __floats2half2_rn(p00.x, p00.y);
        __half2 h1 = __floats2half2_rn(p10.x, p10.y);
        __half2 h2 = __floats2half2_rn(p01.x, p01.y);
        __half2 h3 = __floats2half2_rn(p11.x, p11.y);
        uint32_t* dst = g_Af + (((size_t)(idx >> 5) << 7) + ((idx & 31) << 2));
        *(uint4*)dst = make_uint4(*(uint32_t*)&h0, *(uint32_t*)&h1,
                                  *(uint32_t*)&h2, *(uint32_t*)&h3);
    } else if (bid < ABLKS + WBLKS) {
        int idx  = (bid - ABLKS) * 256 + threadIdx.x;
        int u    = idx & 3;
        int lane = (idx >> 2) & 31;
        int t    = idx >> 7;
        int kt32 = t % KT32;
        int nt   = t / KT32;
        int n    = nt * 8 + (lane >> 2);
        int tg   = lane & 3;
        int kb   = kt32 * 32 + (u >> 1) * 16;
        int k    = kb + 2 * tg + (u & 1) * 8;
        float lo = w_lookup(k, n, W_in_io, W_io_io, W_fast_io, W_io_fast,
                            W_fast_fast, W_slow_fast, W_fast_slow, W_slow_slow,
                            W_io_out);
        float hi = w_lookup(k + 1, n, W_in_io, W_io_io, W_fast_io, W_io_fast,
                            W_fast_fast, W_slow_fast, W_fast_slow, W_slow_slow,
                            W_io_out);
        __half2 h = __floats2half2_rn(lo, hi);
        g_WfragH[idx] = *(uint32_t*)&h;
    } else {
        int n = (bid - ABLKS - WBLKS) * 256 + threadIdx.x;
        if (n >= NPAD) return;
        float v = 0.0f;
        if (n < 64)        v = b_io_out[n];
        else if (n < 576)  { int nn = n - 64;   v = b_in_io[nn] + b_io_io[nn] + b_fast_io[nn]; }
        else if (n < 1088) { int nn = n - 576;  v = b_io_fast[nn] + b_fast_fast[nn] + b_slow_fast[nn]; }
        else if (n < NREAL){ int nn = n - 1088; v = b_slow_slow[nn] + b_fast_slow[nn]; }
        g_bias[n] = v;
    }
}

// ---------------------------------------------------------------------------
__global__ __launch_bounds__(256, 2) void mtrnn_mma(
    const float* __restrict__ io_h, const float* __restrict__ fast_h,
    const float* __restrict__ slow_h, float* __restrict__ out)
{
    extern __shared__ char smem[];
    const uint32_t sb = smem_u32(smem);

    const int tid  = threadIdx.x;
    const int lane = tid & 31;
    const int warp = tid >> 5;
    const int wm   = warp & 1;      // 0..1 : 64-row slab
    const int wn   = warp >> 1;     // 0..3 : 32-col slab
    const int g    = lane >> 2;
    const int tg   = lane & 3;
    (void)g; (void)tg;

    const int n0 = blockIdx.x * 128;
    const int m0 = blockIdx.y * 128;
    const int nt8_0 = blockIdx.x * 16;

    // ---- exact k-range for this n-block (packed W block sparsity) ----
    int nhi = n0 + 128; if (nhi > NREAL) nhi = NREAL;
    int klo = KDIM, khi = 0;
    if (n0 < 64)                 { if (64 < klo) klo = 64;  if (576 > khi) khi = 576; }
    if (n0 < 576 && nhi > 64)    { klo = 0;                 if (1088 > khi) khi = 1088; }
    if (n0 < 1088 && nhi > 576)  { if (64 < klo) klo = 64;  khi = KDIM; }
    if (nhi > 1088)              { if (576 < klo) klo = 576; khi = KDIM; }
    const int kt_lo = klo >> 6;
    const int nkt   = ((khi + 63) >> 6) - kt_lo;    // 12..21

    float acc[4][4][4];             // [mt][nt][frag]
#pragma unroll
    for (int mt = 0; mt < 4; mt++)
#pragma unroll
        for (int nt = 0; nt < 4; nt++)
#pragma unroll
            for (int i = 0; i < 4; i++) acc[mt][nt][i] = 0.0f;

    // ---- walking 32-bit gmem byte offsets (chunk deltas are immediates) ----
    const char* aBase = (const char*)g_Af;
    const char* bBase = (const char*)g_WfragH;
    // A: ktile slab = 16KB contiguous at [(mblk*K16 + kt*4) * 4KB]
    uint32_t aGo = ((uint32_t)blockIdx.y * K16 + (uint32_t)kt_lo * 4) * 4096
                 + (uint32_t)tid * 16;
    // B: chunk i at +i*4*KT32*512; per-ktile stride +1024
    uint32_t bGo = (((uint32_t)(nt8_0 + (tid >> 6)) * KT32
                    + (uint32_t)kt_lo * 2 + ((tid & 63) >> 5)) * 32
                   + (tid & 31)) * 16;
    const uint32_t aSm = sb + (uint32_t)tid * 16;
    const uint32_t bSm = sb + A_BYTES + (uint32_t)tid * 16;

    auto load_slot = [&](int slot) {
        uint32_t so = (uint32_t)slot * STAGE_BYTES;
#pragma unroll
        for (int i = 0; i < 4; i++)
            cpa16(aSm + so + i * 4096, aBase + aGo + i * 4096);
#pragma unroll
        for (int i = 0; i < 4; i++)
            cpa16(bSm + so + i * 4096, bBase + bGo + (uint32_t)i * (4u * KT32 * 512u));
        aGo += 16384; bGo += 1024;
    };

    // one kt2-half (32 k): B 4 LDS.128, A 2 LDS.128 per mt
    auto compute_half = [&](int slot, int h) {
        const uint4*  As4 = (const uint4*)(smem + slot * STAGE_BYTES);
        const float4* Bs4 = (const float4*)(smem + slot * STAGE_BYTES + A_BYTES);
        const int kt2 = h ^ wm;                  // warp-staggered k order
        float4 bf[4];
#pragma unroll
        for (int nt = 0; nt < 4; nt++)
            bf[nt] = Bs4[((wn * 4 + nt) * 2 + kt2) * 32 + lane];
#pragma unroll
        for (int mt = 0; mt < 4; mt++) {
            uint4 f0 = As4[((kt2 * 2 + 0) * 8 + wm * 4 + mt) * 32 + lane];
            uint4 f1 = As4[((kt2 * 2 + 1) * 8 + wm * 4 + mt) * 32 + lane];
#pragma unroll
            for (int nt = 0; nt < 4; nt++) {
                mma_f16(acc[mt][nt], f0.x, f0.y, f0.z, f0.w,
                        __float_as_uint(bf[nt].x), __float_as_uint(bf[nt].y));
                mma_f16(acc[mt][nt], f1.x, f1.y, f1.z, f1.w,
                        __float_as_uint(bf[nt].z), __float_as_uint(bf[nt].w));
            }
        }
    };

    // ---- pipelined mainloop, unrolled by 3 so stage slots are literal ----
    load_slot(0); CP_COMMIT();
    load_slot(1); CP_COMMIT();
    int ld = 2;

#define STEP(J) do {                                   \
        CP_WAIT1(); __syncthreads();                   \
        compute_half(J, 0);                            \
        if (ld < nkt) load_slot(((J) + 2) % 3);        \
        CP_COMMIT();                                   \
        compute_half(J, 1);                            \
        ld++;                                          \
    } while (0)

    int it = 0;
    while (it + 3 <= nkt) { STEP(0); STEP(1); STEP(2); it += 3; }
    if (it < nkt) { STEP(0); it++; }
    if (it < nkt) { STEP(1); it++; }
#undef STEP

    // ---- epilogue: bias + leak + tanh, float2 stores ----
    const int eg  = lane >> 2;
    const int etg = lane & 3;
#pragma unroll
    for (int nt = 0; nt < 4; nt++) {
        int gb = n0 + wn * 32 + nt * 8;
        if (gb >= NREAL) continue;
        int gn = gb + etg * 2;
        float2 bi = *(const float2*)&g_bias[gn];
#pragma unroll
        for (int mt = 0; mt < 4; mt++) {
            int br = m0 + wm * 64 + mt * 16 + eg;
#pragma unroll
            for (int hh = 0; hh < 2; hh++) {
                int b = br + hh * 8;
                float s0 = acc[mt][nt][hh * 2 + 0] + bi.x;
                float s1 = acc[mt][nt][hh * 2 + 1] + bi.y;
                float2 o;
                if (gb < 64) {
                    o.x = tanhf(s0); o.y = tanhf(s1);
                    *(float2*)&out[OFF_OUT + (size_t)b * 64 + gn] = o;
                } else if (gb < 576) {
                    int nn = gn - 64;
                    float2 h = *(const float2*)&io_h[(size_t)b * 512 + nn];
                    o.x = tanhf(0.5f * h.x + 0.5f * s0);
                    o.y = tanhf(0.5f * h.y + 0.5f * s1);
                    *(float2*)&out[OFF_IO + (size_t)b * 512 + nn] = o;
                } else if (gb < 1088) {
                    int nn = gn - 576;
                    float2 h = *(const float2*)&fast_h[(size_t)b * 512 + nn];
                    o.x = tanhf(0.8f * h.x + 0.2f * s0);
                    o.y = tanhf(0.8f * h.y + 0.2f * s1);
                    *(float2*)&out[OFF_FAST + (size_t)b * 512 + nn] = o;
                } else {
                    int nn = gn - 1088;
                    const float cs = 1.0f - 1.0f / 70.0f, is = 1.0f / 70.0f;
                    float2 h = *(const float2*)&slow_h[(size_t)b * 256 + nn];
                    o.x = tanhf(cs * h.x + is * s0);
                    o.y = tanhf(cs * h.y + is * s1);
                    *(float2*)&out[OFF_SLOW + (size_t)b * 256 + nn] = o;
                }
            }
        }
    }
}

// ---------------------------------------------------------------------------
extern "C" void kernel_launch(void* const* d_in, const int* in_sizes, int n_in,
                              void* d_out, int out_size)
{
    const float* input       = (const float*)d_in[0];
    const float* io_h        = (const float*)d_in[1];
    const float* fast_h      = (const float*)d_in[2];
    const float* slow_h      = (const float*)d_in[3];
    const float* W_in_io     = (const float*)d_in[4];
    const float* b_in_io     = (const float*)d_in[5];
    const float* W_io_fast   = (const float*)d_in[6];
    const float* b_io_fast   = (const float*)d_in[7];
    const float* W_fast_fast = (const float*)d_in[8];
    const float* b_fast_fast = (const float*)d_in[9];
    const float* W_fast_slow = (const float*)d_in[10];
    const float* b_fast_slow = (const float*)d_in[11];
    const float* W_slow_slow = (const float*)d_in[12];
    const float* b_slow_slow = (const float*)d_in[13];
    const float* W_slow_fast = (const float*)d_in[14];
    const float* b_slow_fast = (const float*)d_in[15];
    const float* W_fast_io   = (const float*)d_in[16];
    const float* b_fast_io   = (const float*)d_in[17];
    const float* W_io_io     = (const float*)d_in[18];
    const float* b_io_io     = (const float*)d_in[19];
    const float* W_io_out    = (const float*)d_in[20];
    const float* b_io_out    = (const float*)d_in[21];

    cudaFuncSetAttribute(mtrnn_mma, cudaFuncAttributeMaxDynamicSharedMemorySize,
                         SM_TOTAL);

    prep<<<ABLKS + WBLKS + BBLKS, 256>>>(
        input, io_h, fast_h, slow_h,
        W_in_io, W_io_io, W_fast_io, W_io_fast, W_fast_fast,
        W_slow_fast, W_fast_slow, W_slow_slow, W_io_out,
        b_in_io, b_io_io, b_fast_io, b_io_fast, b_fast_fast,
        b_slow_fast, b_fast_slow, b_slow_slow, b_io_out);

    dim3 grid(NPAD / 128, BATCH / 128);
    mtrnn_mma<<<grid, 256, SM_TOTAL>>>(io_h, fast_h, slow_h, (float*)d_out);
}

// round 11
// speedup vs baseline: 1.4183x; 1.1081x over previous
#include <cuda_runtime.h>
#include <cuda_fp16.h>
#include <cstdint>

// ---------------------------------------------------------------------------
// MTRNN cell as ONE block-sparse fp16 GEMM (mma.sync.m16n8k16, legacy path).
// R11 = R10 with the deadlock fixed: cp.async.mbarrier.arrive needs .noinc
// (default variant pre-increments the pending count -- net-zero phase effect,
// so FULLB never completed and all warps spun forever). Protocol re-audited:
// FULL arms/waits 1:1 with one-phase offset; EMPTY wait before reload of
// slot S enforces all-256-threads-done on the tile 3 earlier; tails traced
// for nkt in {12,17,20,21}. Everything else identical to R10/R9.
// ---------------------------------------------------------------------------

#define BATCH 16384
#define KDIM  1344
#define NPAD  1408
#define NREAL 1344
#define NS    3

#define NT8   (NPAD / 8)         // 176
#define KT32  (KDIM / 32)        // 42
#define K16   (KDIM / 16)        // 84

#define OFF_OUT  0
#define OFF_IO   (BATCH * 64)
#define OFF_FAST (OFF_IO + BATCH * 512)
#define OFF_SLOW (OFF_FAST + BATCH * 512)

#define A_BYTES     16384
#define B_BYTES     16384
#define STAGE_BYTES (A_BYTES + B_BYTES)     // 32768
#define MB_OFF      (NS * STAGE_BYTES)      // 98304
#define SM_TOTAL    (MB_OFF + 64)

#define ABLKS 10752
#define WBLKS 3696
#define BBLKS 6

__device__ uint32_t g_Af[(size_t)BATCH * KDIM / 2];
__device__ uint32_t g_WfragH[(size_t)NT8 * KT32 * 32 * 4];
__device__ __align__(16) float g_bias[NPAD];

__device__ __forceinline__ uint32_t smem_u32(const void* p) {
    uint32_t a;
    asm("{ .reg .u64 t; cvta.to.shared.u64 t, %1; cvt.u32.u64 %0, t; }"
        : "=r"(a) : "l"(p));
    return a;
}
__device__ __forceinline__ void cpa16(uint32_t dst, const void* src) {
    asm volatile("cp.async.cg.shared.global [%0], [%1], 16;" :: "r"(dst), "l"(src));
}
__device__ __forceinline__ void mbar_init(uint32_t a, uint32_t cnt) {
    asm volatile("mbarrier.init.shared.b64 [%0], %1;" :: "r"(a), "r"(cnt) : "memory");
}
__device__ __forceinline__ void mbar_arrive(uint32_t a) {
    asm volatile("mbarrier.arrive.shared.b64 _, [%0];" :: "r"(a) : "memory");
}
__device__ __forceinline__ void cpa_mbar_arrive(uint32_t a) {
    // .noinc is load-bearing: default variant pre-increments pending count
    // (net-zero phase effect) and deadlocks a count-256 barrier.
    asm volatile("cp.async.mbarrier.arrive.noinc.shared.b64 [%0];"
                 :: "r"(a) : "memory");
}
__device__ __forceinline__ void mbar_wait(uint32_t a, uint32_t parity) {
    asm volatile(
        "{\n\t.reg .pred P;\n"
        "WL_%=:\n\t"
        "mbarrier.try_wait.parity.shared.b64 P, [%0], %1;\n\t"
        "@P bra WD_%=;\n\t"
        "bra WL_%=;\n"
        "WD_%=:\n\t}"
        :: "r"(a), "r"(parity) : "memory");
}

__device__ __forceinline__ void mma_f16(float* c, uint32_t a0, uint32_t a1,
                                        uint32_t a2, uint32_t a3,
                                        uint32_t b0, uint32_t b1) {
    asm volatile(
        "mma.sync.aligned.m16n8k16.row.col.f32.f16.f16.f32 "
        "{%0,%1,%2,%3}, {%4,%5,%6,%7}, {%8,%9}, {%0,%1,%2,%3};\n"
        : "+f"(c[0]), "+f"(c[1]), "+f"(c[2]), "+f"(c[3])
        : "r"(a0), "r"(a1), "r"(a2), "r"(a3), "r"(b0), "r"(b1));
}

// ---------------------------------------------------------------------------
__device__ __forceinline__ float w_lookup(
    int k, int n,
    const float* W_in_io,   const float* W_io_io,   const float* W_fast_io,
    const float* W_io_fast, const float* W_fast_fast, const float* W_slow_fast,
    const float* W_fast_slow, const float* W_slow_slow, const float* W_io_out)
{
    float v = 0.0f;
    if (n < 64) {
        if (k >= 64 && k < 576)        v = W_io_out[(k - 64) * 64 + n];
    } else if (n < 576) {
        int nn = n - 64;
        if (k < 64)                    v = W_in_io[k * 512 + nn];
        else if (k < 576)              v = W_io_io[(k - 64) * 512 + nn];
        else if (k < 1088)             v = W_fast_io[(k - 576) * 512 + nn];
    } else if (n < 1088) {
        int nn = n - 576;
        if (k >= 64 && k < 576)        v = W_io_fast[(k - 64) * 512 + nn];
        else if (k >= 576 && k < 1088) v = W_fast_fast[(k - 576) * 512 + nn];
        else if (k >= 1088)            v = W_slow_fast[(k - 1088) * 512 + nn];
    } else if (n < NREAL) {
        int nn = n - 1088;
        if (k >= 576 && k < 1088)      v = W_fast_slow[(k - 576) * 256 + nn];
        else if (k >= 1088)            v = W_slow_slow[(k - 1088) * 256 + nn];
    }
    return v;
}

__global__ void prep(
    const float* __restrict__ inp,    const float* __restrict__ io_h,
    const float* __restrict__ fast_h, const float* __restrict__ slow_h,
    const float* __restrict__ W_in_io,   const float* __restrict__ W_io_io,
    const float* __restrict__ W_fast_io, const float* __restrict__ W_io_fast,
    const float* __restrict__ W_fast_fast, const float* __restrict__ W_slow_fast,
    const float* __restrict__ W_fast_slow, const float* __restrict__ W_slow_slow,
    const float* __restrict__ W_io_out,
    const float* __restrict__ b_in_io,   const float* __restrict__ b_io_io,
    const float* __restrict__ b_fast_io, const float* __restrict__ b_io_fast,
    const float* __restrict__ b_fast_fast, const float* __restrict__ b_slow_fast,
    const float* __restrict__ b_fast_slow, const float* __restrict__ b_slow_slow,
    const float* __restrict__ b_io_out)
{
    int bid = blockIdx.x;
    if (bid < ABLKS) {
        int idx     = bid * 256 + threadIdx.x;
        int lane    = idx & 31;
        int rowtile = (idx >> 5) & 7;
        int t       = idx >> 8;
        int k16     = t % K16;
        int mblk    = t / K16;
        int row = mblk * 128 + rowtile * 16 + (lane >> 2);
        int kg  = k16 * 16 + (lane & 3) * 2;
        const float* src; int ld, kb;
        if (kg < 64)        { src = inp;    ld = 64;  kb = kg; }
        else if (kg < 576)  { src = io_h;   ld = 512; kb = kg - 64; }
        else if (kg < 1088) { src = fast_h; ld = 512; kb = kg - 576; }
        else                { src = slow_h; ld = 256; kb = kg - 1088; }
        float2 p00 = *(const float2*)(src + (size_t)row * ld + kb);
        float2 p10 = *(const float2*)(src + (size_t)(row + 8) * ld + kb);
        float2 p01 = *(const float2*)(src + (size_t)row * ld + kb + 8);
        float2 p11 = *(const float2*)(src + (size_t)(row + 8) * ld + kb + 8);
        __half2 h0 = __floats2half2_rn(p00.x, p00.y);
        __half2 h1 = __floats2half2_rn(p10.x, p10.y);
        __half2 h2 = __floats2half2_rn(p01.x, p01.y);
        __half2 h3 = __floats2half2_rn(p11.x, p11.y);
        uint32_t* dst = g_Af + (((size_t)(idx >> 5) << 7) + ((idx & 31) << 2));
        *(uint4*)dst = make_uint4(*(uint32_t*)&h0, *(uint32_t*)&h1,
                                  *(uint32_t*)&h2, *(uint32_t*)&h3);
    } else if (bid < ABLKS + WBLKS) {
        int idx  = (bid - ABLKS) * 256 + threadIdx.x;
        int u    = idx & 3;
        int lane = (idx >> 2) & 31;
        int t    = idx >> 7;
        int kt32 = t % KT32;
        int nt   = t / KT32;
        int n    = nt * 8 + (lane >> 2);
        int tg   = lane & 3;
        int kb   = kt32 * 32 + (u >> 1) * 16;
        int k    = kb + 2 * tg + (u & 1) * 8;
        float lo = w_lookup(k, n, W_in_io, W_io_io, W_fast_io, W_io_fast,
                            W_fast_fast, W_slow_fast, W_fast_slow, W_slow_slow,
                            W_io_out);
        float hi = w_lookup(k + 1, n, W_in_io, W_io_io, W_fast_io, W_io_fast,
                            W_fast_fast, W_slow_fast, W_fast_slow, W_slow_slow,
                            W_io_out);
        __half2 h = __floats2half2_rn(lo, hi);
        g_WfragH[idx] = *(uint32_t*)&h;
    } else {
        int n = (bid - ABLKS - WBLKS) * 256 + threadIdx.x;
        if (n >= NPAD) return;
        float v = 0.0f;
        if (n < 64)        v = b_io_out[n];
        else if (n < 576)  { int nn = n - 64;   v = b_in_io[nn] + b_io_io[nn] + b_fast_io[nn]; }
        else if (n < 1088) { int nn = n - 576;  v = b_io_fast[nn] + b_fast_fast[nn] + b_slow_fast[nn]; }
        else if (n < NREAL){ int nn = n - 1088; v = b_slow_slow[nn] + b_fast_slow[nn]; }
        g_bias[n] = v;
    }
}

// ---------------------------------------------------------------------------
__global__ __launch_bounds__(256, 2) void mtrnn_mma(
    const float* __restrict__ io_h, const float* __restrict__ fast_h,
    const float* __restrict__ slow_h, float* __restrict__ out)
{
    extern __shared__ char smem[];
    const uint32_t sb = smem_u32(smem);

    const int tid  = threadIdx.x;
    const int lane = tid & 31;
    const int warp = tid >> 5;
    const int wm   = warp & 1;      // 0..1 : 64-row slab
    const int wn   = warp >> 1;     // 0..3 : 32-col slab

    const int n0 = blockIdx.x * 128;
    const int m0 = blockIdx.y * 128;
    const int nt8_0 = blockIdx.x * 16;

    // ---- exact k-range for this n-block (packed W block sparsity) ----
    int nhi = n0 + 128; if (nhi > NREAL) nhi = NREAL;
    int klo = KDIM, khi = 0;
    if (n0 < 64)                 { if (64 < klo) klo = 64;  if (576 > khi) khi = 576; }
    if (n0 < 576 && nhi > 64)    { klo = 0;                 if (1088 > khi) khi = 1088; }
    if (n0 < 1088 && nhi > 576)  { if (64 < klo) klo = 64;  khi = KDIM; }
    if (nhi > 1088)              { if (576 < klo) klo = 576; khi = KDIM; }
    const int kt_lo = klo >> 6;
    const int nkt   = ((khi + 63) >> 6) - kt_lo;    // 12..21

    // ---- mbarriers: full[s] / empty[s], 256 arrivals each ----
#define FULLB(S)  (sb + MB_OFF + 8 * (S))
#define EMPTYB(S) (sb + MB_OFF + 24 + 8 * (S))
    if (tid == 0) {
#pragma unroll
        for (int s = 0; s < NS; s++) { mbar_init(FULLB(s), 256); mbar_init(EMPTYB(s), 256); }
    }
    __syncthreads();

    float acc[4][4][4];
#pragma unroll
    for (int mt = 0; mt < 4; mt++)
#pragma unroll
        for (int nt = 0; nt < 4; nt++)
#pragma unroll
            for (int i = 0; i < 4; i++) acc[mt][nt][i] = 0.0f;

    // ---- walking 32-bit gmem byte offsets ----
    const char* aBase = (const char*)g_Af;
    const char* bBase = (const char*)g_WfragH;
    uint32_t aGo = ((uint32_t)blockIdx.y * K16 + (uint32_t)kt_lo * 4) * 4096
                 + (uint32_t)tid * 16;
    uint32_t bGo = (((uint32_t)(nt8_0 + (tid >> 6)) * KT32
                    + (uint32_t)kt_lo * 2 + ((tid & 63) >> 5)) * 32
                   + (tid & 31)) * 16;
    const uint32_t aSm = sb + (uint32_t)tid * 16;
    const uint32_t bSm = sb + A_BYTES + (uint32_t)tid * 16;

    auto load_slot = [&](int slot) {
        uint32_t so = (uint32_t)slot * STAGE_BYTES;
#pragma unroll
        for (int i = 0; i < 4; i++)
            cpa16(aSm + so + i * 4096, aBase + aGo + i * 4096);
#pragma unroll
        for (int i = 0; i < 4; i++)
            cpa16(bSm + so + i * 4096, bBase + bGo + (uint32_t)i * (4u * KT32 * 512u));
        aGo += 16384; bGo += 1024;
    };

    auto compute_half = [&](int slot, int h) {
        const uint4*  As4 = (const uint4*)(smem + slot * STAGE_BYTES);
        const float4* Bs4 = (const float4*)(smem + slot * STAGE_BYTES + A_BYTES);
        const int kt2 = h ^ wm;                  // warp-staggered k order
        float4 bf[4];
#pragma unroll
        for (int nt = 0; nt < 4; nt++)
            bf[nt] = Bs4[((wn * 4 + nt) * 2 + kt2) * 32 + lane];
#pragma unroll
        for (int mt = 0; mt < 4; mt++) {
            uint4 f0 = As4[((kt2 * 2 + 0) * 8 + wm * 4 + mt) * 32 + lane];
            uint4 f1 = As4[((kt2 * 2 + 1) * 8 + wm * 4 + mt) * 32 + lane];
#pragma unroll
            for (int nt = 0; nt < 4; nt++) {
                mma_f16(acc[mt][nt], f0.x, f0.y, f0.z, f0.w,
                        __float_as_uint(bf[nt].x), __float_as_uint(bf[nt].y));
                mma_f16(acc[mt][nt], f1.x, f1.y, f1.z, f1.w,
                        __float_as_uint(bf[nt].z), __float_as_uint(bf[nt].w));
            }
        }
    };

    // ---- mbarrier-gated pipelined mainloop (slots literal via unroll-3) ----
    load_slot(0); cpa_mbar_arrive(FULLB(0));
    load_slot(1); cpa_mbar_arrive(FULLB(1));
    int ld = 2;
    uint32_t fph0 = 0, fph1 = 0, fph2 = 0;       // full parities per slot
    uint32_t eph0 = 0, eph1 = 0, eph2 = 0;       // empty parities per slot

#define FPH(J)  ((J) == 0 ? fph0 : (J) == 1 ? fph1 : fph2)
#define EPH(J)  ((J) == 0 ? eph0 : (J) == 1 ? eph1 : eph2)
#define STEP(J) do {                                                    \
        mbar_wait(FULLB(J), FPH(J)); FPH(J) ^= 1;                       \
        compute_half(J, 0);                                             \
        if (ld < nkt) {                                                 \
            const int SJ = ((J) + 2) % 3;                               \
            if (ld >= 3) { mbar_wait(EMPTYB(SJ), EPH(SJ)); EPH(SJ) ^= 1; } \
            load_slot(SJ); cpa_mbar_arrive(FULLB(SJ));                  \
        }                                                               \
        compute_half(J, 1);                                             \
        mbar_arrive(EMPTYB(J));                                         \
        ld++;                                                           \
    } while (0)

    int it = 0;
    while (it + 3 <= nkt) { STEP(0); STEP(1); STEP(2); it += 3; }
    if (it < nkt) { STEP(0); it++; }
    if (it < nkt) { STEP(1); it++; }
#undef STEP
#undef FPH
#undef EPH

    // ---- epilogue: bias + leak + tanh, float2 stores ----
    const int eg  = lane >> 2;
    const int etg = lane & 3;
#pragma unroll
    for (int nt = 0; nt < 4; nt++) {
        int gb = n0 + wn * 32 + nt * 8;
        if (gb >= NREAL) continue;
        int gn = gb + etg * 2;
        float2 bi = *(const float2*)&g_bias[gn];
#pragma unroll
        for (int mt = 0; mt < 4; mt++) {
            int br = m0 + wm * 64 + mt * 16 + eg;
#pragma unroll
            for (int hh = 0; hh < 2; hh++) {
                int b = br + hh * 8;
                float s0 = acc[mt][nt][hh * 2 + 0] + bi.x;
                float s1 = acc[mt][nt][hh * 2 + 1] + bi.y;
                float2 o;
                if (gb < 64) {
                    o.x = tanhf(s0); o.y = tanhf(s1);
                    *(float2*)&out[OFF_OUT + (size_t)b * 64 + gn] = o;
                } else if (gb < 576) {
                    int nn = gn - 64;
                    float2 h = *(const float2*)&io_h[(size_t)b * 512 + nn];
                    o.x = tanhf(0.5f * h.x + 0.5f * s0);
                    o.y = tanhf(0.5f * h.y + 0.5f * s1);
                    *(float2*)&out[OFF_IO + (size_t)b * 512 + nn] = o;
                } else if (gb < 1088) {
                    int nn = gn - 576;
                    float2 h = *(const float2*)&fast_h[(size_t)b * 512 + nn];
                    o.x = tanhf(0.8f * h.x + 0.2f * s0);
                    o.y = tanhf(0.8f * h.y + 0.2f * s1);
                    *(float2*)&out[OFF_FAST + (size_t)b * 512 + nn] = o;
                } else {
                    int nn = gn - 1088;
                    const float cs = 1.0f - 1.0f / 70.0f, is = 1.0f / 70.0f;
                    float2 h = *(const float2*)&slow_h[(size_t)b * 256 + nn];
                    o.x = tanhf(cs * h.x + is * s0);
                    o.y = tanhf(cs * h.y + is * s1);
                    *(float2*)&out[OFF_SLOW + (size_t)b * 256 + nn] = o;
                }
            }
        }
    }
}

// ---------------------------------------------------------------------------
extern "C" void kernel_launch(void* const* d_in, const int* in_sizes, int n_in,
                              void* d_out, int out_size)
{
    const float* input       = (const float*)d_in[0];
    const float* io_h        = (const float*)d_in[1];
    const float* fast_h      = (const float*)d_in[2];
    const float* slow_h      = (const float*)d_in[3];
    const float* W_in_io     = (const float*)d_in[4];
    const float* b_in_io     = (const float*)d_in[5];
    const float* W_io_fast   = (const float*)d_in[6];
    const float* b_io_fast   = (const float*)d_in[7];
    const float* W_fast_fast = (const float*)d_in[8];
    const float* b_fast_fast = (const float*)d_in[9];
    const float* W_fast_slow = (const float*)d_in[10];
    const float* b_fast_slow = (const float*)d_in[11];
    const float* W_slow_slow = (const float*)d_in[12];
    const float* b_slow_slow = (const float*)d_in[13];
    const float* W_slow_fast = (const float*)d_in[14];
    const float* b_slow_fast = (const float*)d_in[15];
    const float* W_fast_io   = (const float*)d_in[16];
    const float* b_fast_io   = (const float*)d_in[17];
    const float* W_io_io     = (const float*)d_in[18];
    const float* b_io_io     = (const float*)d_in[19];
    const float* W_io_out    = (const float*)d_in[20];
    const float* b_io_out    = (const float*)d_in[21];

    cudaFuncSetAttribute(mtrnn_mma, cudaFuncAttributeMaxDynamicSharedMemorySize,
                         SM_TOTAL);

    prep<<<ABLKS + WBLKS + BBLKS, 256>>>(
        input, io_h, fast_h, slow_h,
        W_in_io, W_io_io, W_fast_io, W_io_fast, W_fast_fast,
        W_slow_fast, W_fast_slow, W_slow_slow, W_io_out,
        b_in_io, b_io_io, b_fast_io, b_io_fast, b_fast_fast,
        b_slow_fast, b_fast_slow, b_slow_slow, b_io_out);

    dim3 grid(NPAD / 128, BATCH / 128);
    mtrnn_mma<<<grid, 256, SM_TOTAL>>>(io_h, fast_h, slow_h, (float*)d_out);
}